// round 16
// baseline (speedup 1.0000x reference)
#include <cuda_runtime.h>
#include <cuda_bf16.h>
#include <math.h>
#include <stdint.h>

// Problem constants
#define B_   4
#define S_   2048
#define DE_  1024
#define NH_  16
#define DH_  64
#define MROWS (B_ * S_)          // 8192
#define N_QKV (3 * DE_)          // 3072

// Scratch (allocation-free rule: __device__ globals)
__device__ float g_qkv[(size_t)MROWS * N_QKV];   // [8192, 3072]
__device__ float g_att[(size_t)MROWS * DE_];     // [8192, 1024]

// ===========================================================================
// mma.sync / ldmatrix helpers (plain PTX, sm_75/80+ -> HMMA/LDSM on sm_103)
// ===========================================================================
__device__ __forceinline__ void mma16816(float* d, const uint32_t* a, const uint32_t* b)
{
    asm volatile(
        "mma.sync.aligned.m16n8k16.row.col.f32.bf16.bf16.f32 "
        "{%0,%1,%2,%3}, {%4,%5,%6,%7}, {%8,%9}, {%0,%1,%2,%3};"
        : "+f"(d[0]), "+f"(d[1]), "+f"(d[2]), "+f"(d[3])
        : "r"(a[0]), "r"(a[1]), "r"(a[2]), "r"(a[3]), "r"(b[0]), "r"(b[1]));
}

__device__ __forceinline__ void ldsm_x4(uint32_t* r, uint32_t addr)
{
    asm volatile(
        "ldmatrix.sync.aligned.m8n8.x4.shared.b16 {%0,%1,%2,%3}, [%4];"
        : "=r"(r[0]), "=r"(r[1]), "=r"(r[2]), "=r"(r[3]) : "r"(addr));
}

__device__ __forceinline__ uint32_t smem_to_u32(const void* p) {
    uint32_t a;
    asm("{ .reg .u64 t; cvta.to.shared.u64 t, %1; cvt.u32.u64 %0, t; }"
        : "=r"(a) : "l"(p));
    return a;
}

// pack two fp32 -> bf16x2 (x0 in low half)
__device__ __forceinline__ uint32_t pack_bf16x2(float x0, float x1)
{
    uint32_t r;
    asm("cvt.rn.bf16x2.f32 %0, %1, %2;" : "=r"(r) : "f"(x1), "f"(x0));
    return r;
}
__device__ __forceinline__ float bflo(uint32_t p) { return __uint_as_float(p << 16); }
__device__ __forceinline__ float bfhi(uint32_t p) { return __uint_as_float(p & 0xffff0000u); }

// ===========================================================================
// GEMM: C[M,N] = A[M,K] @ W[N,K]^T + bias[N], fp32 via bf16-split mma.sync.
// R16: CTA 128x128, BK=32, 4 warps (2x2), warp tile 64x64.
// 16 LDSM feed 96 MMAs per warp-k16 (0.042 B/MAC vs 0.063 before) --
// attacks the L1-wavefront bound seen at R15 (L1=81.6%, tensor=52.6%).
// ===========================================================================
#define WS 20
#define GBM 128
#define GBN 128
#define GBK 32

__global__ __launch_bounds__(128, 2) void gemm_mma_kernel(
    const float* __restrict__ A, const float* __restrict__ W,
    const float* __restrict__ bias, float* __restrict__ C,
    int M, int N, int K)
{
    __shared__ uint32_t sAh[128 * WS], sAl[128 * WS];
    __shared__ uint32_t sWh[128 * WS], sWl[128 * WS];   // 40KB

    const int tid  = threadIdx.x;
    const int lane = tid & 31;
    const int wid  = tid >> 5;          // 0..3
    const int wm   = wid >> 1;          // 0..1 (64 M-rows)
    const int wn   = wid & 1;           // 0..1 (64 N-cols)
    const int bm   = blockIdx.y * GBM;
    const int bn   = blockIdx.x * GBN;

    float acc[4][8][4];
    #pragma unroll
    for (int mi = 0; mi < 4; mi++)
        #pragma unroll
        for (int ni = 0; ni < 8; ni++)
            #pragma unroll
            for (int e = 0; e < 4; e++) acc[mi][ni][e] = 0.f;

    // gmem: thread t owns full row t of both A and W tiles (32 floats each)
    const float* Ap = A + (size_t)(bm + tid) * K;
    const float* Wp = W + (size_t)(bn + tid) * K;
    const int sw = tid * WS;

    // ldmatrix per-lane address bases (bytes), loop-invariant.
    // A x4 tile order: (m0-7,k0-7)(m8-15,k0-7)(m0-7,k8-15)(m8-15,k8-15)
    const int a_row = wm * 64 + (lane & 7) + ((lane >> 3) & 1) * 8;
    const int a_col = ((lane >> 4) & 1) * 4;
    const uint32_t aAh = smem_to_u32(sAh) + (uint32_t)(a_row * WS + a_col) * 4;
    const uint32_t aAl = smem_to_u32(sAl) + (uint32_t)(a_row * WS + a_col) * 4;
    // B x4 packs an n-block pair: (nblo k0-7)(nblo k8-15)(nbhi k0-7)(nbhi k8-15)
    const int b_row = wn * 64 + ((lane >> 4) & 1) * 8 + (lane & 7);
    const int b_col = ((lane >> 3) & 1) * 4;
    const uint32_t aWh = smem_to_u32(sWh) + (uint32_t)(b_row * WS + b_col) * 4;
    const uint32_t aWl = smem_to_u32(sWl) + (uint32_t)(b_row * WS + b_col) * 4;

    for (int k0 = 0; k0 < K; k0 += GBK) {
        // ---- global loads (32 floats per operand per thread) ----
        float av[32], wv[32];
        #pragma unroll
        for (int i = 0; i < 8; i++) {
            *reinterpret_cast<float4*>(&av[4 * i]) =
                *reinterpret_cast<const float4*>(Ap + k0 + 4 * i);
            *reinterpret_cast<float4*>(&wv[4 * i]) =
                *reinterpret_cast<const float4*>(Wp + k0 + 4 * i);
        }

        __syncthreads();   // previous iteration's fragment reads complete

        // ---- split to bf16 hi/lo and store (full row per thread) ----
        {
            uint32_t ah[16], al[16], wh[16], wl[16];
            #pragma unroll
            for (int p = 0; p < 16; p++) {
                float x0 = av[2 * p], x1 = av[2 * p + 1];
                uint32_t hp = pack_bf16x2(x0, x1);
                ah[p] = hp;
                al[p] = pack_bf16x2(x0 - bflo(hp), x1 - bfhi(hp));

                float y0 = wv[2 * p], y1 = wv[2 * p + 1];
                uint32_t hq = pack_bf16x2(y0, y1);
                wh[p] = hq;
                wl[p] = pack_bf16x2(y0 - bflo(hq), y1 - bfhi(hq));
            }
            #pragma unroll
            for (int i = 0; i < 4; i++) {
                *reinterpret_cast<uint4*>(&sAh[sw + 4 * i]) =
                    make_uint4(ah[4 * i], ah[4 * i + 1], ah[4 * i + 2], ah[4 * i + 3]);
                *reinterpret_cast<uint4*>(&sAl[sw + 4 * i]) =
                    make_uint4(al[4 * i], al[4 * i + 1], al[4 * i + 2], al[4 * i + 3]);
                *reinterpret_cast<uint4*>(&sWh[sw + 4 * i]) =
                    make_uint4(wh[4 * i], wh[4 * i + 1], wh[4 * i + 2], wh[4 * i + 3]);
                *reinterpret_cast<uint4*>(&sWl[sw + 4 * i]) =
                    make_uint4(wl[4 * i], wl[4 * i + 1], wl[4 * i + 2], wl[4 * i + 3]);
            }
        }
        __syncthreads();

        // ---- 2 k16 steps x 3 split terms ----
        #pragma unroll
        for (int s = 0; s < 2; s++) {
            const uint32_t so = (uint32_t)(s * 8) * 4;   // byte offset along k
            uint32_t bh[8][2], bl[8][2], af[4][4];

            // B fragments: 4 x4 per array (each covers an n-block pair)
            #pragma unroll
            for (int nbp = 0; nbp < 4; nbp++) {
                const uint32_t po = so + (uint32_t)(nbp * 16 * WS) * 4;
                uint32_t q[4];
                ldsm_x4(q, aWh + po);
                bh[2 * nbp][0] = q[0]; bh[2 * nbp][1] = q[1];
                bh[2 * nbp + 1][0] = q[2]; bh[2 * nbp + 1][1] = q[3];
                ldsm_x4(q, aWl + po);
                bl[2 * nbp][0] = q[0]; bl[2 * nbp][1] = q[1];
                bl[2 * nbp + 1][0] = q[2]; bl[2 * nbp + 1][1] = q[3];
            }
            // A hi fragments
            #pragma unroll
            for (int mi = 0; mi < 4; mi++)
                ldsm_x4(af[mi], aAh + so + (uint32_t)(mi * 16 * WS) * 4);
            #pragma unroll
            for (int mi = 0; mi < 4; mi++)
                #pragma unroll
                for (int ni = 0; ni < 8; ni++) {
                    mma16816(acc[mi][ni], af[mi], bh[ni]);
                    mma16816(acc[mi][ni], af[mi], bl[ni]);
                }
            // A lo fragments (reuse regs)
            #pragma unroll
            for (int mi = 0; mi < 4; mi++)
                ldsm_x4(af[mi], aAl + so + (uint32_t)(mi * 16 * WS) * 4);
            #pragma unroll
            for (int mi = 0; mi < 4; mi++)
                #pragma unroll
                for (int ni = 0; ni < 8; ni++)
                    mma16816(acc[mi][ni], af[mi], bh[ni]);
        }
    }

    // ---- epilogue: acc + bias -> C ----
    const int fr = lane >> 2;
    const int fc = lane & 3;
    #pragma unroll
    for (int ni = 0; ni < 8; ni++) {
        const int col = bn + wn * 64 + ni * 8 + fc * 2;
        const float2 bv = *reinterpret_cast<const float2*>(&bias[col]);
        #pragma unroll
        for (int mi = 0; mi < 4; mi++) {
            const int row = bm + wm * 64 + mi * 16 + fr;
            float2 o0, o1;
            o0.x = acc[mi][ni][0] + bv.x; o0.y = acc[mi][ni][1] + bv.y;
            o1.x = acc[mi][ni][2] + bv.x; o1.y = acc[mi][ni][3] + bv.y;
            *reinterpret_cast<float2*>(C + (size_t)row * N + col)       = o0;
            *reinterpret_cast<float2*>(C + (size_t)(row + 8) * N + col) = o1;
        }
    }
}

// ===========================================================================
// Flash attention (causal) on mma.sync, bf16-split for QK^T and PV.
// (unchanged from R10/R15)
// ===========================================================================
#define AST 36
#define ATTN_SMEM_BYTES (6 * 64 * AST * 4)   // 55296

__global__ __launch_bounds__(128) void attn_mma_kernel(
    const float* __restrict__ qkv, float* __restrict__ out)
{
    extern __shared__ uint32_t sm[];
    uint32_t* sQh = sm;
    uint32_t* sQl = sQh + 64 * AST;
    uint32_t* sKh = sQl + 64 * AST;
    uint32_t* sKl = sKh + 64 * AST;
    uint32_t* sVh = sKl + 64 * AST;   // [d][kp]
    uint32_t* sVl = sVh + 64 * AST;

    const int STR = 3 * DE_;
    const int qt = blockIdx.x;
    const int h  = blockIdx.y;
    const int b  = blockIdx.z;

    const float* Qg = qkv + (size_t)b * S_ * STR + h * DH_;
    const float* Kg = Qg + DE_;
    const float* Vg = Qg + 2 * DE_;

    const int tid  = threadIdx.x;
    const int lane = tid & 31;
    const int wid  = tid >> 5;
    const int fr   = lane >> 2;
    const int fc   = lane & 3;

    // ---- load Q tile (rows qt*64..+64), split hi/lo ----
    {
        const int r = tid >> 1, half = tid & 1;
        const float* qrow = Qg + (size_t)(qt * 64 + r) * STR + half * 32;
        uint32_t hb[16], lb[16];
        #pragma unroll
        for (int i = 0; i < 8; i++) {
            float4 v = *reinterpret_cast<const float4*>(qrow + 4 * i);
            uint32_t h0 = pack_bf16x2(v.x, v.y);
            uint32_t h1 = pack_bf16x2(v.z, v.w);
            hb[2 * i]     = h0;
            hb[2 * i + 1] = h1;
            lb[2 * i]     = pack_bf16x2(v.x - bflo(h0), v.y - bfhi(h0));
            lb[2 * i + 1] = pack_bf16x2(v.z - bflo(h1), v.w - bfhi(h1));
        }
        const int base = r * AST + half * 16;
        #pragma unroll
        for (int i = 0; i < 4; i++) {
            *reinterpret_cast<uint4*>(&sQh[base + 4 * i]) =
                make_uint4(hb[4 * i], hb[4 * i + 1], hb[4 * i + 2], hb[4 * i + 3]);
            *reinterpret_cast<uint4*>(&sQl[base + 4 * i]) =
                make_uint4(lb[4 * i], lb[4 * i + 1], lb[4 * i + 2], lb[4 * i + 3]);
        }
    }

    float o[8][4];
    #pragma unroll
    for (int d = 0; d < 8; d++)
        #pragma unroll
        for (int e = 0; e < 4; e++) o[d][e] = 0.f;
    float m0 = -INFINITY, m1 = -INFINITY, l0 = 0.f, l1 = 0.f;

    for (int kt = 0; kt <= qt; kt++) {
        __syncthreads();

        // ---- load K tile (split, [k'][d]) ----
        {
            const int r = tid >> 1, half = tid & 1;
            const float* krow = Kg + (size_t)(kt * 64 + r) * STR + half * 32;
            uint32_t hb[16], lb[16];
            #pragma unroll
            for (int i = 0; i < 8; i++) {
                float4 v = *reinterpret_cast<const float4*>(krow + 4 * i);
                uint32_t h0 = pack_bf16x2(v.x, v.y);
                uint32_t h1 = pack_bf16x2(v.z, v.w);
                hb[2 * i]     = h0;
                hb[2 * i + 1] = h1;
                lb[2 * i]     = pack_bf16x2(v.x - bflo(h0), v.y - bfhi(h0));
                lb[2 * i + 1] = pack_bf16x2(v.z - bflo(h1), v.w - bfhi(h1));
            }
            const int base = r * AST + half * 16;
            #pragma unroll
            for (int i = 0; i < 4; i++) {
                *reinterpret_cast<uint4*>(&sKh[base + 4 * i]) =
                    make_uint4(hb[4 * i], hb[4 * i + 1], hb[4 * i + 2], hb[4 * i + 3]);
                *reinterpret_cast<uint4*>(&sKl[base + 4 * i]) =
                    make_uint4(lb[4 * i], lb[4 * i + 1], lb[4 * i + 2], lb[4 * i + 3]);
            }
        }
        // ---- load V tile transposed (split, [d][k-pairs]) ----
        {
            const int kp = tid & 31;
            const int db = (tid >> 5) * 16;
            const float* v0 = Vg + (size_t)(kt * 64 + 2 * kp) * STR + db;
            const float* v1 = v0 + STR;
            #pragma unroll
            for (int i = 0; i < 4; i++) {
                float4 a = *reinterpret_cast<const float4*>(v0 + 4 * i);
                float4 c = *reinterpret_cast<const float4*>(v1 + 4 * i);
                float ae[4] = {a.x, a.y, a.z, a.w};
                float ce[4] = {c.x, c.y, c.z, c.w};
                #pragma unroll
                for (int e = 0; e < 4; e++) {
                    const int d = db + 4 * i + e;
                    uint32_t hp = pack_bf16x2(ae[e], ce[e]);
                    sVh[d * AST + kp] = hp;
                    sVl[d * AST + kp] = pack_bf16x2(ae[e] - bflo(hp), ce[e] - bfhi(hp));
                }
            }
        }
        __syncthreads();

        // ---- S = Q K^T (3-term split) ----
        float s[8][4];
        #pragma unroll
        for (int nb = 0; nb < 8; nb++)
            #pragma unroll
            for (int e = 0; e < 4; e++) s[nb][e] = 0.f;

        #pragma unroll
        for (int ks = 0; ks < 4; ks++) {
            uint32_t ah[4], al[4];
            const int ab = (wid * 16 + fr) * AST + ks * 8 + fc;
            ah[0] = sQh[ab];           ah[1] = sQh[ab + 8 * AST];
            ah[2] = sQh[ab + 4];       ah[3] = sQh[ab + 8 * AST + 4];
            al[0] = sQl[ab];           al[1] = sQl[ab + 8 * AST];
            al[2] = sQl[ab + 4];       al[3] = sQl[ab + 8 * AST + 4];
            #pragma unroll
            for (int nb = 0; nb < 8; nb++) {
                const int bb = (nb * 8 + fr) * AST + ks * 8 + fc;
                uint32_t bh[2] = {sKh[bb], sKh[bb + 4]};
                uint32_t bl[2] = {sKl[bb], sKl[bb + 4]};
                mma16816(s[nb], ah, bh);
                mma16816(s[nb], ah, bl);
                mma16816(s[nb], al, bh);
            }
        }

        // ---- scale, causal mask, online softmax ----
        const bool diag = (kt == qt);
        const int r0 = wid * 16 + fr;
        const int r1 = r0 + 8;
        float mx0 = -INFINITY, mx1 = -INFINITY;
        #pragma unroll
        for (int nb = 0; nb < 8; nb++) {
            const int c0 = nb * 8 + 2 * fc, c1 = c0 + 1;
            float v0 = s[nb][0] * 0.125f, v1 = s[nb][1] * 0.125f;
            float v2 = s[nb][2] * 0.125f, v3 = s[nb][3] * 0.125f;
            if (diag) {
                if (c0 > r0) v0 = -INFINITY;
                if (c1 > r0) v1 = -INFINITY;
                if (c0 > r1) v2 = -INFINITY;
                if (c1 > r1) v3 = -INFINITY;
            }
            s[nb][0] = v0; s[nb][1] = v1; s[nb][2] = v2; s[nb][3] = v3;
            mx0 = fmaxf(mx0, fmaxf(v0, v1));
            mx1 = fmaxf(mx1, fmaxf(v2, v3));
        }
        mx0 = fmaxf(mx0, __shfl_xor_sync(0xffffffffu, mx0, 1));
        mx0 = fmaxf(mx0, __shfl_xor_sync(0xffffffffu, mx0, 2));
        mx1 = fmaxf(mx1, __shfl_xor_sync(0xffffffffu, mx1, 1));
        mx1 = fmaxf(mx1, __shfl_xor_sync(0xffffffffu, mx1, 2));

        const float m0n = fmaxf(m0, mx0);
        const float m1n = fmaxf(m1, mx1);
        const float rs0 = __expf(m0 - m0n);
        const float rs1 = __expf(m1 - m1n);
        m0 = m0n; m1 = m1n;

        float sum0 = 0.f, sum1 = 0.f;
        #pragma unroll
        for (int nb = 0; nb < 8; nb++) {
            float p0 = __expf(s[nb][0] - m0);
            float p1 = __expf(s[nb][1] - m0);
            float p2 = __expf(s[nb][2] - m1);
            float p3 = __expf(s[nb][3] - m1);
            s[nb][0] = p0; s[nb][1] = p1; s[nb][2] = p2; s[nb][3] = p3;
            sum0 += p0 + p1;
            sum1 += p2 + p3;
        }
        sum0 += __shfl_xor_sync(0xffffffffu, sum0, 1);
        sum0 += __shfl_xor_sync(0xffffffffu, sum0, 2);
        sum1 += __shfl_xor_sync(0xffffffffu, sum1, 1);
        sum1 += __shfl_xor_sync(0xffffffffu, sum1, 2);
        l0 = l0 * rs0 + sum0;
        l1 = l1 * rs1 + sum1;

        #pragma unroll
        for (int d = 0; d < 8; d++) {
            o[d][0] *= rs0; o[d][1] *= rs0;
            o[d][2] *= rs1; o[d][3] *= rs1;
        }

        // ---- O += P V (P register-direct; 3-term split) ----
        #pragma unroll
        for (int kc = 0; kc < 4; kc++) {
            uint32_t ph[4], pl[4];
            const float* pA = s[2 * kc];
            const float* pB = s[2 * kc + 1];
            ph[0] = pack_bf16x2(pA[0], pA[1]);
            ph[1] = pack_bf16x2(pA[2], pA[3]);
            ph[2] = pack_bf16x2(pB[0], pB[1]);
            ph[3] = pack_bf16x2(pB[2], pB[3]);
            pl[0] = pack_bf16x2(pA[0] - bflo(ph[0]), pA[1] - bfhi(ph[0]));
            pl[1] = pack_bf16x2(pA[2] - bflo(ph[1]), pA[3] - bfhi(ph[1]));
            pl[2] = pack_bf16x2(pB[0] - bflo(ph[2]), pB[1] - bfhi(ph[2]));
            pl[3] = pack_bf16x2(pB[2] - bflo(ph[3]), pB[3] - bfhi(ph[3]));
            #pragma unroll
            for (int db = 0; db < 8; db++) {
                const int bb = (db * 8 + fr) * AST + kc * 8 + fc;
                uint32_t bh[2] = {sVh[bb], sVh[bb + 4]};
                uint32_t bl[2] = {sVl[bb], sVl[bb + 4]};
                mma16816(o[db], ph, bh);
                mma16816(o[db], ph, bl);
                mma16816(o[db], pl, bh);
            }
        }
    }

    // ---- epilogue ----
    const float inv0 = 1.f / l0;
    const float inv1 = 1.f / l1;
    const int row0 = qt * 64 + wid * 16 + fr;
    float* out0 = out + ((size_t)b * S_ + row0) * DE_ + h * DH_;
    float* out1 = out0 + (size_t)8 * DE_;
    #pragma unroll
    for (int db = 0; db < 8; db++) {
        const int col = db * 8 + 2 * fc;
        float2 w0, w1;
        w0.x = o[db][0] * inv0; w0.y = o[db][1] * inv0;
        w1.x = o[db][2] * inv1; w1.y = o[db][3] * inv1;
        *reinterpret_cast<float2*>(out0 + col) = w0;
        *reinterpret_cast<float2*>(out1 + col) = w1;
    }
}

// ---------------------------------------------------------------------------
extern "C" void kernel_launch(void* const* d_in, const int* in_sizes, int n_in,
                              void* d_out, int out_size)
{
    const float* x     = (const float*)d_in[0];
    const float* W_in  = (const float*)d_in[1];
    const float* b_in  = (const float*)d_in[2];
    const float* W_out = (const float*)d_in[3];
    const float* b_out = (const float*)d_in[4];
    float* out = (float*)d_out;

    float* qkv = nullptr;
    float* att = nullptr;
    cudaGetSymbolAddress((void**)&qkv, g_qkv);
    cudaGetSymbolAddress((void**)&att, g_att);

    cudaFuncSetAttribute(attn_mma_kernel,
                         cudaFuncAttributeMaxDynamicSharedMemorySize,
                         ATTN_SMEM_BYTES);

    // 1) QKV projection: [8192,3072] = x @ W_in^T + b_in
    {
        dim3 grid(N_QKV / GBN, MROWS / GBM);
        gemm_mma_kernel<<<grid, 128>>>(x, W_in, b_in, qkv, MROWS, N_QKV, DE_);
    }
    // 2) Causal flash attention -> att [8192,1024]
    {
        dim3 grid(S_ / 64, NH_, B_);
        attn_mma_kernel<<<grid, 128, ATTN_SMEM_BYTES>>>(qkv, att);
    }
    // 3) Output projection: out = att @ W_out^T + b_out
    {
        dim3 grid(DE_ / GBN, MROWS / GBM);
        gemm_mma_kernel<<<grid, 128>>>(att, W_out, b_out, out, MROWS, DE_, DE_);
    }
}

// round 17
// speedup vs baseline: 1.3032x; 1.3032x over previous
#include <cuda_runtime.h>
#include <cuda_bf16.h>
#include <math.h>
#include <stdint.h>

// Problem constants
#define B_   4
#define S_   2048
#define DE_  1024
#define NH_  16
#define DH_  64
#define MROWS (B_ * S_)          // 8192
#define N_QKV (3 * DE_)          // 3072

// Scratch (allocation-free rule: __device__ globals)
__device__ float g_qkv[(size_t)MROWS * N_QKV];   // [8192, 3072]
__device__ float g_att[(size_t)MROWS * DE_];     // [8192, 1024]

// ===========================================================================
// mma.sync / ldmatrix helpers (plain PTX, sm_75/80+ -> HMMA/LDSM on sm_103)
// ===========================================================================
__device__ __forceinline__ void mma16816(float* d, const uint32_t* a, const uint32_t* b)
{
    asm volatile(
        "mma.sync.aligned.m16n8k16.row.col.f32.bf16.bf16.f32 "
        "{%0,%1,%2,%3}, {%4,%5,%6,%7}, {%8,%9}, {%0,%1,%2,%3};"
        : "+f"(d[0]), "+f"(d[1]), "+f"(d[2]), "+f"(d[3])
        : "r"(a[0]), "r"(a[1]), "r"(a[2]), "r"(a[3]), "r"(b[0]), "r"(b[1]));
}

__device__ __forceinline__ void ldsm_x4(uint32_t* r, uint32_t addr)
{
    asm volatile(
        "ldmatrix.sync.aligned.m8n8.x4.shared.b16 {%0,%1,%2,%3}, [%4];"
        : "=r"(r[0]), "=r"(r[1]), "=r"(r[2]), "=r"(r[3]) : "r"(addr));
}

__device__ __forceinline__ uint32_t smem_to_u32(const void* p) {
    uint32_t a;
    asm("{ .reg .u64 t; cvta.to.shared.u64 t, %1; cvt.u32.u64 %0, t; }"
        : "=r"(a) : "l"(p));
    return a;
}

// pack two fp32 -> bf16x2 (x0 in low half)
__device__ __forceinline__ uint32_t pack_bf16x2(float x0, float x1)
{
    uint32_t r;
    asm("cvt.rn.bf16x2.f32 %0, %1, %2;" : "=r"(r) : "f"(x1), "f"(x0));
    return r;
}
__device__ __forceinline__ float bflo(uint32_t p) { return __uint_as_float(p << 16); }
__device__ __forceinline__ float bfhi(uint32_t p) { return __uint_as_float(p & 0xffff0000u); }

// ===========================================================================
// GEMM: C[M,N] = A[M,K] @ W[N,K]^T + bias[N], fp32 via bf16-split mma.sync.
// R15 config verbatim (best measured: QKV 487us, tensor 52.6%):
// CTA 128x128, BK=32, 8 warps (2M x 4N), warp tile 64x32, single-buffered,
// ldmatrix.x4 fragment loads.
// ===========================================================================
#define WS 20
#define GBM 128
#define GBN 128
#define GBK 32

__global__ __launch_bounds__(256, 2) void gemm_mma_kernel(
    const float* __restrict__ A, const float* __restrict__ W,
    const float* __restrict__ bias, float* __restrict__ C,
    int M, int N, int K)
{
    __shared__ uint32_t sAh[128 * WS], sAl[128 * WS];
    __shared__ uint32_t sWh[128 * WS], sWl[128 * WS];

    const int tid  = threadIdx.x;
    const int lane = tid & 31;
    const int wid  = tid >> 5;
    const int wm   = wid >> 2;
    const int wn   = wid & 3;
    const int bm   = blockIdx.y * GBM;
    const int bn   = blockIdx.x * GBN;

    float acc[4][4][4];
    #pragma unroll
    for (int mi = 0; mi < 4; mi++)
        #pragma unroll
        for (int ni = 0; ni < 4; ni++)
            #pragma unroll
            for (int e = 0; e < 4; e++) acc[mi][ni][e] = 0.f;

    const int lrow = tid >> 1;
    const int lh   = tid & 1;
    const float* Ap = A + (size_t)(bm + lrow) * K + lh * 16;
    const float* Wp = W + (size_t)(bn + lrow) * K + lh * 16;
    const int sw = lrow * WS + lh * 8;

    // ldmatrix per-lane address bases (bytes), loop-invariant.
    const int a_row = wm * 64 + (lane & 7) + ((lane >> 3) & 1) * 8;
    const int a_col = ((lane >> 4) & 1) * 4;
    const uint32_t aAh = smem_to_u32(sAh) + (uint32_t)(a_row * WS + a_col) * 4;
    const uint32_t aAl = smem_to_u32(sAl) + (uint32_t)(a_row * WS + a_col) * 4;
    const int b_row = wn * 32 + ((lane >> 4) & 1) * 8 + (lane & 7);
    const int b_col = ((lane >> 3) & 1) * 4;
    const uint32_t aWh = smem_to_u32(sWh) + (uint32_t)(b_row * WS + b_col) * 4;
    const uint32_t aWl = smem_to_u32(sWl) + (uint32_t)(b_row * WS + b_col) * 4;

    for (int k0 = 0; k0 < K; k0 += GBK) {
        float av[16], wv[16];
        #pragma unroll
        for (int i = 0; i < 4; i++) {
            *reinterpret_cast<float4*>(&av[4 * i]) =
                *reinterpret_cast<const float4*>(Ap + k0 + 4 * i);
            *reinterpret_cast<float4*>(&wv[4 * i]) =
                *reinterpret_cast<const float4*>(Wp + k0 + 4 * i);
        }

        __syncthreads();

        {
            uint32_t ah[8], al[8], wh[8], wl[8];
            #pragma unroll
            for (int p = 0; p < 8; p++) {
                float x0 = av[2 * p], x1 = av[2 * p + 1];
                uint32_t hp = pack_bf16x2(x0, x1);
                ah[p] = hp;
                al[p] = pack_bf16x2(x0 - bflo(hp), x1 - bfhi(hp));

                float y0 = wv[2 * p], y1 = wv[2 * p + 1];
                uint32_t hq = pack_bf16x2(y0, y1);
                wh[p] = hq;
                wl[p] = pack_bf16x2(y0 - bflo(hq), y1 - bfhi(hq));
            }
            *reinterpret_cast<uint4*>(&sAh[sw])     = make_uint4(ah[0], ah[1], ah[2], ah[3]);
            *reinterpret_cast<uint4*>(&sAh[sw + 4]) = make_uint4(ah[4], ah[5], ah[6], ah[7]);
            *reinterpret_cast<uint4*>(&sAl[sw])     = make_uint4(al[0], al[1], al[2], al[3]);
            *reinterpret_cast<uint4*>(&sAl[sw + 4]) = make_uint4(al[4], al[5], al[6], al[7]);
            *reinterpret_cast<uint4*>(&sWh[sw])     = make_uint4(wh[0], wh[1], wh[2], wh[3]);
            *reinterpret_cast<uint4*>(&sWh[sw + 4]) = make_uint4(wh[4], wh[5], wh[6], wh[7]);
            *reinterpret_cast<uint4*>(&sWl[sw])     = make_uint4(wl[0], wl[1], wl[2], wl[3]);
            *reinterpret_cast<uint4*>(&sWl[sw + 4]) = make_uint4(wl[4], wl[5], wl[6], wl[7]);
        }
        __syncthreads();

        #pragma unroll
        for (int s = 0; s < 2; s++) {
            const uint32_t so = (uint32_t)(s * 8) * 4;
            uint32_t bh[4][2], bl[4][2], af[4][4];

            {
                uint32_t q[4];
                ldsm_x4(q, aWh + so);
                bh[0][0] = q[0]; bh[0][1] = q[1]; bh[1][0] = q[2]; bh[1][1] = q[3];
                ldsm_x4(q, aWh + so + (uint32_t)(16 * WS) * 4);
                bh[2][0] = q[0]; bh[2][1] = q[1]; bh[3][0] = q[2]; bh[3][1] = q[3];
                ldsm_x4(q, aWl + so);
                bl[0][0] = q[0]; bl[0][1] = q[1]; bl[1][0] = q[2]; bl[1][1] = q[3];
                ldsm_x4(q, aWl + so + (uint32_t)(16 * WS) * 4);
                bl[2][0] = q[0]; bl[2][1] = q[1]; bl[3][0] = q[2]; bl[3][1] = q[3];
            }
            #pragma unroll
            for (int mi = 0; mi < 4; mi++)
                ldsm_x4(af[mi], aAh + so + (uint32_t)(mi * 16 * WS) * 4);
            #pragma unroll
            for (int mi = 0; mi < 4; mi++)
                #pragma unroll
                for (int ni = 0; ni < 4; ni++) {
                    mma16816(acc[mi][ni], af[mi], bh[ni]);
                    mma16816(acc[mi][ni], af[mi], bl[ni]);
                }
            #pragma unroll
            for (int mi = 0; mi < 4; mi++)
                ldsm_x4(af[mi], aAl + so + (uint32_t)(mi * 16 * WS) * 4);
            #pragma unroll
            for (int mi = 0; mi < 4; mi++)
                #pragma unroll
                for (int ni = 0; ni < 4; ni++)
                    mma16816(acc[mi][ni], af[mi], bh[ni]);
        }
    }

    const int fr = lane >> 2;
    const int fc = lane & 3;
    #pragma unroll
    for (int ni = 0; ni < 4; ni++) {
        const int col = bn + wn * 32 + ni * 8 + fc * 2;
        const float2 bv = *reinterpret_cast<const float2*>(&bias[col]);
        #pragma unroll
        for (int mi = 0; mi < 4; mi++) {
            const int row = bm + wm * 64 + mi * 16 + fr;
            float2 o0, o1;
            o0.x = acc[mi][ni][0] + bv.x; o0.y = acc[mi][ni][1] + bv.y;
            o1.x = acc[mi][ni][2] + bv.x; o1.y = acc[mi][ni][3] + bv.y;
            *reinterpret_cast<float2*>(C + (size_t)row * N + col)       = o0;
            *reinterpret_cast<float2*>(C + (size_t)(row + 8) * N + col) = o1;
        }
    }
}

// ===========================================================================
// Flash attention (causal) on mma.sync, bf16-split.
// R17: CTA = 128 q-rows (8 warps x 16 rows), 64-col K/V tiles.
// Halves K/V load+convert work per q-row (272 vs 528 tile-iters per b,h),
// raises occupancy to 24 warps/SM (72KB smem -> 3 CTA/SM).
// Per-warp diagonal guard skips fully-masked tiles (no syncs inside).
// ===========================================================================
#define AST 36
#define ATTN_QR 128
// words: Qh/Ql 128*AST each, Kh/Kl/Vh/Vl 64*AST each = 512*AST
#define ATTN_SMEM_BYTES (512 * AST * 4)   // 73728

__global__ __launch_bounds__(256) void attn_mma_kernel(
    const float* __restrict__ qkv, float* __restrict__ out)
{
    extern __shared__ uint32_t sm[];
    uint32_t* sQh = sm;
    uint32_t* sQl = sQh + 128 * AST;
    uint32_t* sKh = sQl + 128 * AST;
    uint32_t* sKl = sKh + 64 * AST;
    uint32_t* sVh = sKl + 64 * AST;   // [d][kp]
    uint32_t* sVl = sVh + 64 * AST;

    const int STR = 3 * DE_;
    const int qt = blockIdx.x;        // 0..15 (128-row q tiles)
    const int h  = blockIdx.y;
    const int b  = blockIdx.z;

    const float* Qg = qkv + (size_t)b * S_ * STR + h * DH_;
    const float* Kg = Qg + DE_;
    const float* Vg = Qg + 2 * DE_;

    const int tid  = threadIdx.x;
    const int lane = tid & 31;
    const int wid  = tid >> 5;        // 0..7
    const int fr   = lane >> 2;
    const int fc   = lane & 3;

    // ---- load Q tile (rows qt*128..+128), split hi/lo ----
    {
        const int r = tid >> 1, half = tid & 1;
        const float* qrow = Qg + (size_t)(qt * ATTN_QR + r) * STR + half * 32;
        uint32_t hb[16], lb[16];
        #pragma unroll
        for (int i = 0; i < 8; i++) {
            float4 v = *reinterpret_cast<const float4*>(qrow + 4 * i);
            uint32_t h0 = pack_bf16x2(v.x, v.y);
            uint32_t h1 = pack_bf16x2(v.z, v.w);
            hb[2 * i]     = h0;
            hb[2 * i + 1] = h1;
            lb[2 * i]     = pack_bf16x2(v.x - bflo(h0), v.y - bfhi(h0));
            lb[2 * i + 1] = pack_bf16x2(v.z - bflo(h1), v.w - bfhi(h1));
        }
        const int base = r * AST + half * 16;
        #pragma unroll
        for (int i = 0; i < 4; i++) {
            *reinterpret_cast<uint4*>(&sQh[base + 4 * i]) =
                make_uint4(hb[4 * i], hb[4 * i + 1], hb[4 * i + 2], hb[4 * i + 3]);
            *reinterpret_cast<uint4*>(&sQl[base + 4 * i]) =
                make_uint4(lb[4 * i], lb[4 * i + 1], lb[4 * i + 2], lb[4 * i + 3]);
        }
    }

    float o[8][4];
    #pragma unroll
    for (int d = 0; d < 8; d++)
        #pragma unroll
        for (int e = 0; e < 4; e++) o[d][e] = 0.f;
    float m0 = -INFINITY, m1 = -INFINITY, l0 = 0.f, l1 = 0.f;

    const int qrow_min = qt * ATTN_QR + wid * 16;   // this warp's first q row
    const int ktmax = 2 * qt + 1;

    for (int kt = 0; kt <= ktmax; kt++) {
        __syncthreads();   // prior-iter K/V reads done (also Q stores, 1st iter)

        // ---- load K tile (split, [k'][d]); 256 thr, 16 floats each ----
        {
            const int r = tid >> 2, q4 = tid & 3;
            const float* krow = Kg + (size_t)(kt * 64 + r) * STR + q4 * 16;
            uint32_t hb[8], lb[8];
            #pragma unroll
            for (int i = 0; i < 4; i++) {
                float4 v = *reinterpret_cast<const float4*>(krow + 4 * i);
                uint32_t h0 = pack_bf16x2(v.x, v.y);
                uint32_t h1 = pack_bf16x2(v.z, v.w);
                hb[2 * i]     = h0;
                hb[2 * i + 1] = h1;
                lb[2 * i]     = pack_bf16x2(v.x - bflo(h0), v.y - bfhi(h0));
                lb[2 * i + 1] = pack_bf16x2(v.z - bflo(h1), v.w - bfhi(h1));
            }
            const int base = r * AST + q4 * 8;
            *reinterpret_cast<uint4*>(&sKh[base])     = make_uint4(hb[0], hb[1], hb[2], hb[3]);
            *reinterpret_cast<uint4*>(&sKh[base + 4]) = make_uint4(hb[4], hb[5], hb[6], hb[7]);
            *reinterpret_cast<uint4*>(&sKl[base])     = make_uint4(lb[0], lb[1], lb[2], lb[3]);
            *reinterpret_cast<uint4*>(&sKl[base + 4]) = make_uint4(lb[4], lb[5], lb[6], lb[7]);
        }
        // ---- load V tile transposed (split, [d][k-pairs]); 8 d per warp ----
        {
            const int kp = tid & 31;
            const int db = (tid >> 5) * 8;
            const float* v0 = Vg + (size_t)(kt * 64 + 2 * kp) * STR + db;
            const float* v1 = v0 + STR;
            #pragma unroll
            for (int i = 0; i < 2; i++) {
                float4 a = *reinterpret_cast<const float4*>(v0 + 4 * i);
                float4 c = *reinterpret_cast<const float4*>(v1 + 4 * i);
                float ae[4] = {a.x, a.y, a.z, a.w};
                float ce[4] = {c.x, c.y, c.z, c.w};
                #pragma unroll
                for (int e = 0; e < 4; e++) {
                    const int d = db + 4 * i + e;
                    uint32_t hp = pack_bf16x2(ae[e], ce[e]);
                    sVh[d * AST + kp] = hp;
                    sVl[d * AST + kp] = pack_bf16x2(ae[e] - bflo(hp), ce[e] - bfhi(hp));
                }
            }
        }
        __syncthreads();

        // Per-warp guard: skip tiles entirely above this warp's rows.
        // (No block syncs inside the guarded region.)
        if (kt * 64 <= qrow_min + 15) {
            // ---- S = Q K^T (3-term split) ----
            float s[8][4];
            #pragma unroll
            for (int nb = 0; nb < 8; nb++)
                #pragma unroll
                for (int e = 0; e < 4; e++) s[nb][e] = 0.f;

            #pragma unroll
            for (int ks = 0; ks < 4; ks++) {
                uint32_t ah[4], al[4];
                const int ab = (wid * 16 + fr) * AST + ks * 8 + fc;
                ah[0] = sQh[ab];           ah[1] = sQh[ab + 8 * AST];
                ah[2] = sQh[ab + 4];       ah[3] = sQh[ab + 8 * AST + 4];
                al[0] = sQl[ab];           al[1] = sQl[ab + 8 * AST];
                al[2] = sQl[ab + 4];       al[3] = sQl[ab + 8 * AST + 4];
                #pragma unroll
                for (int nb = 0; nb < 8; nb++) {
                    const int bb = (nb * 8 + fr) * AST + ks * 8 + fc;
                    uint32_t bh[2] = {sKh[bb], sKh[bb + 4]};
                    uint32_t bl[2] = {sKl[bb], sKl[bb + 4]};
                    mma16816(s[nb], ah, bh);
                    mma16816(s[nb], ah, bl);
                    mma16816(s[nb], al, bh);
                }
            }

            // ---- scale, causal mask (global idx), online softmax ----
            const bool needMask = (kt * 64 + 63 > qrow_min);
            const int r0g = qrow_min + fr;
            const int r1g = r0g + 8;
            float mx0 = -INFINITY, mx1 = -INFINITY;
            #pragma unroll
            for (int nb = 0; nb < 8; nb++) {
                const int c0 = kt * 64 + nb * 8 + 2 * fc, c1 = c0 + 1;
                float v0 = s[nb][0] * 0.125f, v1 = s[nb][1] * 0.125f;
                float v2 = s[nb][2] * 0.125f, v3 = s[nb][3] * 0.125f;
                if (needMask) {
                    if (c0 > r0g) v0 = -INFINITY;
                    if (c1 > r0g) v1 = -INFINITY;
                    if (c0 > r1g) v2 = -INFINITY;
                    if (c1 > r1g) v3 = -INFINITY;
                }
                s[nb][0] = v0; s[nb][1] = v1; s[nb][2] = v2; s[nb][3] = v3;
                mx0 = fmaxf(mx0, fmaxf(v0, v1));
                mx1 = fmaxf(mx1, fmaxf(v2, v3));
            }
            mx0 = fmaxf(mx0, __shfl_xor_sync(0xffffffffu, mx0, 1));
            mx0 = fmaxf(mx0, __shfl_xor_sync(0xffffffffu, mx0, 2));
            mx1 = fmaxf(mx1, __shfl_xor_sync(0xffffffffu, mx1, 1));
            mx1 = fmaxf(mx1, __shfl_xor_sync(0xffffffffu, mx1, 2));

            const float m0n = fmaxf(m0, mx0);
            const float m1n = fmaxf(m1, mx1);
            const float rs0 = __expf(m0 - m0n);
            const float rs1 = __expf(m1 - m1n);
            m0 = m0n; m1 = m1n;

            float sum0 = 0.f, sum1 = 0.f;
            #pragma unroll
            for (int nb = 0; nb < 8; nb++) {
                float p0 = __expf(s[nb][0] - m0);
                float p1 = __expf(s[nb][1] - m0);
                float p2 = __expf(s[nb][2] - m1);
                float p3 = __expf(s[nb][3] - m1);
                s[nb][0] = p0; s[nb][1] = p1; s[nb][2] = p2; s[nb][3] = p3;
                sum0 += p0 + p1;
                sum1 += p2 + p3;
            }
            sum0 += __shfl_xor_sync(0xffffffffu, sum0, 1);
            sum0 += __shfl_xor_sync(0xffffffffu, sum0, 2);
            sum1 += __shfl_xor_sync(0xffffffffu, sum1, 1);
            sum1 += __shfl_xor_sync(0xffffffffu, sum1, 2);
            l0 = l0 * rs0 + sum0;
            l1 = l1 * rs1 + sum1;

            #pragma unroll
            for (int d = 0; d < 8; d++) {
                o[d][0] *= rs0; o[d][1] *= rs0;
                o[d][2] *= rs1; o[d][3] *= rs1;
            }

            // ---- O += P V (P register-direct; 3-term split) ----
            #pragma unroll
            for (int kc = 0; kc < 4; kc++) {
                uint32_t ph[4], pl[4];
                const float* pA = s[2 * kc];
                const float* pB = s[2 * kc + 1];
                ph[0] = pack_bf16x2(pA[0], pA[1]);
                ph[1] = pack_bf16x2(pA[2], pA[3]);
                ph[2] = pack_bf16x2(pB[0], pB[1]);
                ph[3] = pack_bf16x2(pB[2], pB[3]);
                pl[0] = pack_bf16x2(pA[0] - bflo(ph[0]), pA[1] - bfhi(ph[0]));
                pl[1] = pack_bf16x2(pA[2] - bflo(ph[1]), pA[3] - bfhi(ph[1]));
                pl[2] = pack_bf16x2(pB[0] - bflo(ph[2]), pB[1] - bfhi(ph[2]));
                pl[3] = pack_bf16x2(pB[2] - bflo(ph[3]), pB[3] - bfhi(ph[3]));
                #pragma unroll
                for (int db = 0; db < 8; db++) {
                    const int bb = (db * 8 + fr) * AST + kc * 8 + fc;
                    uint32_t bh[2] = {sVh[bb], sVh[bb + 4]};
                    uint32_t bl[2] = {sVl[bb], sVl[bb + 4]};
                    mma16816(o[db], ph, bh);
                    mma16816(o[db], ph, bl);
                    mma16816(o[db], pl, bh);
                }
            }
        }
    }

    // ---- epilogue ----
    const float inv0 = 1.f / l0;
    const float inv1 = 1.f / l1;
    const int row0 = qrow_min + fr;
    float* out0 = out + ((size_t)b * S_ + row0) * DE_ + h * DH_;
    float* out1 = out0 + (size_t)8 * DE_;
    #pragma unroll
    for (int db = 0; db < 8; db++) {
        const int col = db * 8 + 2 * fc;
        float2 w0, w1;
        w0.x = o[db][0] * inv0; w0.y = o[db][1] * inv0;
        w1.x = o[db][2] * inv1; w1.y = o[db][3] * inv1;
        *reinterpret_cast<float2*>(out0 + col) = w0;
        *reinterpret_cast<float2*>(out1 + col) = w1;
    }
}

// ---------------------------------------------------------------------------
extern "C" void kernel_launch(void* const* d_in, const int* in_sizes, int n_in,
                              void* d_out, int out_size)
{
    const float* x     = (const float*)d_in[0];
    const float* W_in  = (const float*)d_in[1];
    const float* b_in  = (const float*)d_in[2];
    const float* W_out = (const float*)d_in[3];
    const float* b_out = (const float*)d_in[4];
    float* out = (float*)d_out;

    float* qkv = nullptr;
    float* att = nullptr;
    cudaGetSymbolAddress((void**)&qkv, g_qkv);
    cudaGetSymbolAddress((void**)&att, g_att);

    cudaFuncSetAttribute(attn_mma_kernel,
                         cudaFuncAttributeMaxDynamicSharedMemorySize,
                         ATTN_SMEM_BYTES);

    // 1) QKV projection: [8192,3072] = x @ W_in^T + b_in
    {
        dim3 grid(N_QKV / GBN, MROWS / GBM);
        gemm_mma_kernel<<<grid, 256>>>(x, W_in, b_in, qkv, MROWS, N_QKV, DE_);
    }
    // 2) Causal flash attention -> att [8192,1024]
    {
        dim3 grid(S_ / ATTN_QR, NH_, B_);
        attn_mma_kernel<<<grid, 256, ATTN_SMEM_BYTES>>>(qkv, att);
    }
    // 3) Output projection: out = att @ W_out^T + b_out
    {
        dim3 grid(DE_ / GBN, MROWS / GBM);
        gemm_mma_kernel<<<grid, 256>>>(att, W_out, b_out, out, MROWS, DE_, DE_);
    }
}